// round 5
// baseline (speedup 1.0000x reference)
#include <cuda_runtime.h>

// SSIM loss, single fused kernel. U/V transform: u=p+t, v=p-t, so only
// 2 packed f32x2 conv fields: X=(u,v), Y=(u^2,v^2).
//   A=conv(u), B=conv(v), C=conv(u2), D=conv(v2)
//   2*m12=(A^2-B^2)/2, m1s+m2s=(A^2+B^2)/2,
//   2*s12=(C-D)/2-2*m12, s1+s2=(C+D)/2-(m1s+m2s)
// Tile 32W x 64H (halo 5) in dynamic smem; last-block-done reduction
// (threadfence + counter) replaces the separate finish kernel.

#define TW    32
#define TH    64
#define HALO  5
#define EW    42              // TW + 10
#define EH    74              // TH + 10
#define XP    43              // pitch (ull) input tile
#define HP    33              // pitch (ull) h-pass arrays

#define IMG_H 512
#define IMG_W 512
#define N_PLANES 96
#define GX    16
#define GY    8
#define NBLK  (GX*GY*N_PLANES)   // 12288
#define N_PIX 25165824.0

#define SX_OFF   0
#define HX_OFF   (EH*XP*8)             // 25456
#define HY_OFF   (HX_OFF + EH*HP*8)    // 44992
#define RED_OFF  (HY_OFF + EH*HP*8)    // 64528
#define SMEM_TOTAL (RED_OFF + 16*4 + 16)

typedef unsigned long long ull;

__device__ constexpr float GW[11] = {
    0.00102838f, 0.00759877f, 0.03600077f, 0.10936071f, 0.21300553f,
    0.26601175f,
    0.21300553f, 0.10936071f, 0.03600077f, 0.00759877f, 0.00102838f
};

__device__ float g_part[NBLK];
__device__ unsigned int g_count;

__device__ __forceinline__ ull pk2(float lo, float hi) {
    ull r;
    asm("mov.b64 %0, {%1, %2};" : "=l"(r) : "f"(lo), "f"(hi));
    return r;
}
__device__ __forceinline__ void upk2(float& lo, float& hi, ull v) {
    asm("mov.b64 {%0, %1}, %2;" : "=f"(lo), "=f"(hi) : "l"(v));
}
__device__ __forceinline__ void fma2(ull& d, ull a, ull b) {
    asm("fma.rn.f32x2 %0, %1, %2, %0;" : "+l"(d) : "l"(a), "l"(b));
}
__device__ __forceinline__ ull mul2(ull a, ull b) {
    ull d;
    asm("mul.rn.f32x2 %0, %1, %2;" : "=l"(d) : "l"(a), "l"(b));
    return d;
}

__global__ __launch_bounds__(512, 2)
void ssim_tile_kernel(const float* __restrict__ pred,
                      const float* __restrict__ targ,
                      float* __restrict__ out)
{
    extern __shared__ char smem[];
    ull  (*sX)[XP] = (ull(*)[XP])(smem + SX_OFF);
    ull  (*hX)[HP] = (ull(*)[HP])(smem + HX_OFF);
    ull  (*hY)[HP] = (ull(*)[HP])(smem + HY_OFF);
    float* red     = (float*)(smem + RED_OFF);
    int*   lastflag = (int*)(smem + RED_OFF + 16*4);

    const int tid = threadIdx.x;
    const int ty0 = blockIdx.y * TH;
    const int tx0 = blockIdx.x * TW;
    const size_t pbase = (size_t)blockIdx.z * (IMG_H * IMG_W);

    // ---- load halo tile, compute (u,v), store packed ----
    #pragma unroll
    for (int it = 0; it < 7; it++) {
        int idx = tid + it * 512;
        if (idx < EH * EW) {
            int r = idx / EW;
            int c = idx - r * EW;
            int gy = ty0 + r - HALO;
            int gx = tx0 + c - HALO;
            bool ok = ((unsigned)gy < (unsigned)IMG_H) & ((unsigned)gx < (unsigned)IMG_W);
            float a = 0.f, b = 0.f;
            if (ok) {
                size_t off = pbase + (size_t)gy * IMG_W + gx;
                a = pred[off];
                b = targ[off];
            }
            sX[r][c] = pk2(a + b, a - b);
        }
    }
    __syncthreads();

    // ---- horizontal pass: 74 rows x 8 quad-groups = 592 items ----
    for (int g = tid; g < EH * (TW / 4); g += 512) {
        const int r  = g >> 3;
        const int c0 = (g & 7) * 4;
        ull aX[4] = {0, 0, 0, 0};
        ull aY[4] = {0, 0, 0, 0};

        #pragma unroll
        for (int i = 0; i < 14; i++) {
            ull X = sX[r][c0 + i];
            ull Y = mul2(X, X);
            #pragma unroll
            for (int j = 0; j < 4; j++) {
                int k = i - j;
                if (k >= 0 && k <= 10) {
                    ull w2 = pk2(GW[k], GW[k]);
                    fma2(aX[j], X, w2);
                    fma2(aY[j], Y, w2);
                }
            }
        }
        #pragma unroll
        for (int j = 0; j < 4; j++) {
            hX[r][c0 + j] = aX[j];
            hY[r][c0 + j] = aY[j];
        }
    }
    __syncthreads();

    // ---- vertical pass + SSIM: thread -> (x, 4 adjacent y) ----
    const int x  = tid & 31;
    const int y0 = (tid >> 5) * 4;     // 0..60

    ull vX[4] = {0, 0, 0, 0};
    ull vY[4] = {0, 0, 0, 0};

    #pragma unroll
    for (int i = 0; i < 14; i++) {
        int row = y0 + i;
        ull cX = hX[row][x];
        ull cY = hY[row][x];
        #pragma unroll
        for (int j = 0; j < 4; j++) {
            int k = i - j;
            if (k >= 0 && k <= 10) {
                ull w2 = pk2(GW[k], GW[k]);
                fma2(vX[j], cX, w2);
                fma2(vY[j], cY, w2);
            }
        }
    }

    float lsum = 0.f;
    const float C1 = 1e-4f;
    const float C2 = 9e-4f;
    #pragma unroll
    for (int j = 0; j < 4; j++) {
        float A, B, Cv, Dv;
        upk2(A, B, vX[j]);
        upk2(Cv, Dv, vY[j]);
        float A2 = A * A;
        float B2 = B * B;
        float t2m12 = (A2 - B2) * 0.5f;
        float msum  = (A2 + B2) * 0.5f;
        float t2s12 = (Cv - Dv) * 0.5f - t2m12;
        float ssum  = (Cv + Dv) * 0.5f - msum;
        float num = (t2m12 + C1) * (t2s12 + C2);
        float den = (msum + C1) * (ssum + C2) + 1e-8f;
        lsum += __fdividef(num, den);
    }

    // ---- block reduce, write unique partial slot ----
    #pragma unroll
    for (int o = 16; o; o >>= 1)
        lsum += __shfl_xor_sync(0xffffffffu, lsum, o);
    if ((tid & 31) == 0) red[tid >> 5] = lsum;
    __syncthreads();

    if (tid == 0) {
        float s = 0.f;
        #pragma unroll
        for (int w = 0; w < 16; w++) s += red[w];
        int bid = (blockIdx.z * GY + blockIdx.y) * GX + blockIdx.x;
        g_part[bid] = s;
        __threadfence();
        unsigned int prev = atomicAdd(&g_count, 1u);
        *lastflag = (prev == NBLK - 1) ? 1 : 0;
    }
    __syncthreads();

    // ---- last block: final reduction over all partials ----
    if (*lastflag) {
        __threadfence();
        const float4* p4 = (const float4*)g_part;
        float s = 0.f;
        #pragma unroll
        for (int it = 0; it < 6; it++) {
            float4 v = p4[tid + it * 512];
            s += (v.x + v.y) + (v.z + v.w);
        }
        #pragma unroll
        for (int o = 16; o; o >>= 1)
            s += __shfl_xor_sync(0xffffffffu, s, o);
        if ((tid & 31) == 0) red[tid >> 5] = s;
        __syncthreads();
        if (tid == 0) {
            float t = 0.f;
            #pragma unroll
            for (int w = 0; w < 16; w++) t += red[w];
            out[0] = (float)(1.0 - (double)t * (1.0 / N_PIX));
            g_count = 0;   // self-reset for next graph replay
        }
    }
}

extern "C" void kernel_launch(void* const* d_in, const int* in_sizes, int n_in,
                              void* d_out, int out_size)
{
    const float* pred = (const float*)d_in[0];
    const float* targ = (const float*)d_in[1];

    cudaFuncSetAttribute(ssim_tile_kernel,
                         cudaFuncAttributeMaxDynamicSharedMemorySize, SMEM_TOTAL);
    dim3 grid(GX, GY, N_PLANES);   // 16 x 8 x 96
    ssim_tile_kernel<<<grid, 512, SMEM_TOTAL>>>(pred, targ, (float*)d_out);
}

// round 6
// speedup vs baseline: 1.0527x; 1.0527x over previous
#include <cuda_runtime.h>

// SSIM loss, single fused kernel. U/V transform: u=p+t, v=p-t ->
// 2 packed f32x2 conv fields X=(u,v), Y=(u2,v2).
//   A=conv(u), B=conv(v), C=conv(u2), D=conv(v2)
//   2*m12=(A^2-B^2)/2, m1s+m2s=(A^2+B^2)/2,
//   2*s12=(C-D)/2-2*m12, s1+s2=(C+D)/2-(m1s+m2s)
// h-pass results stored as one interleaved 16B record (A,B,C,D): v-pass is
// ONE LDS.128 per tap (half the LSU issue slots of 2x LDS.64).
// 64.6KB smem, __launch_bounds__(512,3) -> 3 blocks/SM (72% occ).
// Last-block-done final reduction (no separate kernel).

#define TW    32
#define TH    64
#define HALO  5
#define EW    42
#define EH    74
#define XP    43              // pitch (ull) input tile
#define HP    33              // pitch (ulonglong2) h-pass array

#define IMG_H 512
#define IMG_W 512
#define N_PLANES 96
#define GX    16
#define GY    8
#define NBLK  (GX*GY*N_PLANES)   // 12288
#define N_PIX 25165824.0

#define SX_OFF   0
#define HQ_OFF   (EH*XP*8)             // 25456
#define RED_OFF  (HQ_OFF + EH*HP*16)   // 64528
#define SMEM_TOTAL (RED_OFF + 16*4 + 16)

typedef unsigned long long ull;

__device__ constexpr float GW[11] = {
    0.00102838f, 0.00759877f, 0.03600077f, 0.10936071f, 0.21300553f,
    0.26601175f,
    0.21300553f, 0.10936071f, 0.03600077f, 0.00759877f, 0.00102838f
};

__device__ float g_part[NBLK];
__device__ unsigned int g_count;

__device__ __forceinline__ ull pk2(float lo, float hi) {
    ull r;
    asm("mov.b64 %0, {%1, %2};" : "=l"(r) : "f"(lo), "f"(hi));
    return r;
}
__device__ __forceinline__ void upk2(float& lo, float& hi, ull v) {
    asm("mov.b64 {%0, %1}, %2;" : "=f"(lo), "=f"(hi) : "l"(v));
}
__device__ __forceinline__ void fma2(ull& d, ull a, ull b) {
    asm("fma.rn.f32x2 %0, %1, %2, %0;" : "+l"(d) : "l"(a), "l"(b));
}
__device__ __forceinline__ ull mul2(ull a, ull b) {
    ull d;
    asm("mul.rn.f32x2 %0, %1, %2;" : "=l"(d) : "l"(a), "l"(b));
    return d;
}

__global__ __launch_bounds__(512, 3)
void ssim_tile_kernel(const float* __restrict__ pred,
                      const float* __restrict__ targ,
                      float* __restrict__ out)
{
    extern __shared__ char smem[];
    ull         (*sX)[XP] = (ull(*)[XP])(smem + SX_OFF);
    ulonglong2  (*hQ)[HP] = (ulonglong2(*)[HP])(smem + HQ_OFF);
    float* red    = (float*)(smem + RED_OFF);
    int* lastflag = (int*)(smem + RED_OFF + 16*4);

    const int tid = threadIdx.x;
    const int ty0 = blockIdx.y * TH;
    const int tx0 = blockIdx.x * TW;
    const size_t pbase = (size_t)blockIdx.z * (IMG_H * IMG_W);

    // ---- load halo tile, compute (u,v), store packed ----
    #pragma unroll
    for (int it = 0; it < 7; it++) {
        int idx = tid + it * 512;
        if (idx < EH * EW) {
            int r = idx / EW;
            int c = idx - r * EW;
            int gy = ty0 + r - HALO;
            int gx = tx0 + c - HALO;
            bool ok = ((unsigned)gy < (unsigned)IMG_H) & ((unsigned)gx < (unsigned)IMG_W);
            float a = 0.f, b = 0.f;
            if (ok) {
                size_t off = pbase + (size_t)gy * IMG_W + gx;
                a = pred[off];
                b = targ[off];
            }
            sX[r][c] = pk2(a + b, a - b);
        }
    }
    __syncthreads();

    // ---- horizontal pass: 74 rows x 8 quad-groups = 592 items ----
    #pragma unroll
    for (int it = 0; it < 2; it++) {
        int g = tid + it * 512;
        if (g < EH * (TW / 4)) {
            const int r  = g >> 3;
            const int c0 = (g & 7) * 4;
            ull aX[4] = {0, 0, 0, 0};
            ull aY[4] = {0, 0, 0, 0};

            #pragma unroll
            for (int i = 0; i < 14; i++) {
                ull X = sX[r][c0 + i];
                ull Y = mul2(X, X);
                #pragma unroll
                for (int j = 0; j < 4; j++) {
                    int k = i - j;
                    if (k >= 0 && k <= 10) {
                        ull w2 = pk2(GW[k], GW[k]);
                        fma2(aX[j], X, w2);
                        fma2(aY[j], Y, w2);
                    }
                }
            }
            #pragma unroll
            for (int j = 0; j < 4; j++) {
                ulonglong2 q; q.x = aX[j]; q.y = aY[j];
                hQ[r][c0 + j] = q;      // one STS.128
            }
        }
    }
    __syncthreads();

    // ---- vertical pass + SSIM: thread -> (x, 4 adjacent y) ----
    const int x  = tid & 31;
    const int y0 = (tid >> 5) * 4;     // 0..60

    ull vX[4] = {0, 0, 0, 0};
    ull vY[4] = {0, 0, 0, 0};

    #pragma unroll
    for (int i = 0; i < 14; i++) {
        ulonglong2 q = hQ[y0 + i][x];  // one LDS.128 per tap
        #pragma unroll
        for (int j = 0; j < 4; j++) {
            int k = i - j;
            if (k >= 0 && k <= 10) {
                ull w2 = pk2(GW[k], GW[k]);
                fma2(vX[j], q.x, w2);
                fma2(vY[j], q.y, w2);
            }
        }
    }

    float lsum = 0.f;
    const float C1 = 1e-4f;
    const float C2 = 9e-4f;
    #pragma unroll
    for (int j = 0; j < 4; j++) {
        float A, B, Cv, Dv;
        upk2(A, B, vX[j]);
        upk2(Cv, Dv, vY[j]);
        float A2 = A * A;
        float B2 = B * B;
        float t2m12 = (A2 - B2) * 0.5f;
        float msum  = (A2 + B2) * 0.5f;
        float t2s12 = (Cv - Dv) * 0.5f - t2m12;
        float ssum  = (Cv + Dv) * 0.5f - msum;
        float num = (t2m12 + C1) * (t2s12 + C2);
        float den = (msum + C1) * (ssum + C2) + 1e-8f;
        lsum += __fdividef(num, den);
    }

    // ---- block reduce, unique partial slot ----
    #pragma unroll
    for (int o = 16; o; o >>= 1)
        lsum += __shfl_xor_sync(0xffffffffu, lsum, o);
    if ((tid & 31) == 0) red[tid >> 5] = lsum;
    __syncthreads();

    if (tid == 0) {
        float s = 0.f;
        #pragma unroll
        for (int w = 0; w < 16; w++) s += red[w];
        int bid = (blockIdx.z * GY + blockIdx.y) * GX + blockIdx.x;
        g_part[bid] = s;
        __threadfence();
        unsigned int prev = atomicAdd(&g_count, 1u);
        *lastflag = (prev == NBLK - 1) ? 1 : 0;
    }
    __syncthreads();

    // ---- last block: final reduction over all partials ----
    if (*lastflag) {
        __threadfence();
        const float4* p4 = (const float4*)g_part;
        float s = 0.f;
        #pragma unroll
        for (int it = 0; it < 6; it++) {
            float4 v = p4[tid + it * 512];
            s += (v.x + v.y) + (v.z + v.w);
        }
        #pragma unroll
        for (int o = 16; o; o >>= 1)
            s += __shfl_xor_sync(0xffffffffu, s, o);
        if ((tid & 31) == 0) red[tid >> 5] = s;
        __syncthreads();
        if (tid == 0) {
            float t = 0.f;
            #pragma unroll
            for (int w = 0; w < 16; w++) t += red[w];
            out[0] = (float)(1.0 - (double)t * (1.0 / N_PIX));
            g_count = 0;   // self-reset for next graph replay
        }
    }
}

extern "C" void kernel_launch(void* const* d_in, const int* in_sizes, int n_in,
                              void* d_out, int out_size)
{
    const float* pred = (const float*)d_in[0];
    const float* targ = (const float*)d_in[1];

    cudaFuncSetAttribute(ssim_tile_kernel,
                         cudaFuncAttributeMaxDynamicSharedMemorySize, SMEM_TOTAL);
    dim3 grid(GX, GY, N_PLANES);   // 16 x 8 x 96
    ssim_tile_kernel<<<grid, 512, SMEM_TOTAL>>>(pred, targ, (float*)d_out);
}

// round 7
// speedup vs baseline: 1.3940x; 1.3242x over previous
#include <cuda_runtime.h>
#include <cuda_fp16.h>

// SSIM loss, single fused kernel, fp16 datapath.
// U/V transform: u=p+t, v=p-t -> conv fields X=(u,v), Y=(u2,v2) as half2.
//   A=conv(u), B=conv(v), C=conv(u2), D=conv(v2)   (HFMA2 convs)
//   2*m12=(A^2-B^2)/2, m1s+m2s=(A^2+B^2)/2,
//   2*s12=(C-D)/2-2*m12, s1+s2=(C+D)/2-(m1s+m2s)   (fp32 SSIM formula)
// sX: half2 (4B/px, conflict-free h-pass LDS.32). hQ: 8B record -> v-pass
// is one LDS.64 per tap. smem 32.4KB. Last-block-done final reduction.

#define TW    32
#define TH    64
#define HALO  5
#define EW    42
#define EH    74
#define XP    43              // pitch (half2) input tile
#define HP    33              // pitch (8B rec) h-pass array

#define IMG_H 512
#define IMG_W 512
#define N_PLANES 96
#define GX    16
#define GY    8
#define NBLK  (GX*GY*N_PLANES)   // 12288
#define N_PIX 25165824.0

#define SX_OFF   0
#define HQ_OFF   (EH*XP*4)             // 12728
#define RED_OFF  (HQ_OFF + EH*HP*8)    // 32264
#define SMEM_TOTAL (RED_OFF + 16*4 + 16)

__device__ constexpr float GW[11] = {
    0.00102838f, 0.00759877f, 0.03600077f, 0.10936071f, 0.21300553f,
    0.26601175f,
    0.21300553f, 0.10936071f, 0.03600077f, 0.00759877f, 0.00102838f
};

struct __align__(8) HQrec { __half2 ab; __half2 cd; };

__device__ float g_part[NBLK];
__device__ unsigned int g_count;

__global__ __launch_bounds__(512, 3)
void ssim_tile_kernel(const float* __restrict__ pred,
                      const float* __restrict__ targ,
                      float* __restrict__ out)
{
    extern __shared__ char smem[];
    __half2 (*sX)[XP] = (__half2(*)[XP])(smem + SX_OFF);
    HQrec   (*hQ)[HP] = (HQrec(*)[HP])(smem + HQ_OFF);
    float* red    = (float*)(smem + RED_OFF);
    int* lastflag = (int*)(smem + RED_OFF + 16*4);

    const int tid = threadIdx.x;
    const int ty0 = blockIdx.y * TH;
    const int tx0 = blockIdx.x * TW;
    const size_t pbase = (size_t)blockIdx.z * (IMG_H * IMG_W);

    // ---- load halo tile, compute (u,v), store half2 ----
    #pragma unroll
    for (int it = 0; it < 7; it++) {
        int idx = tid + it * 512;
        if (idx < EH * EW) {
            int r = idx / EW;
            int c = idx - r * EW;
            int gy = ty0 + r - HALO;
            int gx = tx0 + c - HALO;
            bool ok = ((unsigned)gy < (unsigned)IMG_H) & ((unsigned)gx < (unsigned)IMG_W);
            float a = 0.f, b = 0.f;
            if (ok) {
                size_t off = pbase + (size_t)gy * IMG_W + gx;
                a = pred[off];
                b = targ[off];
            }
            sX[r][c] = __floats2half2_rn(a + b, a - b);
        }
    }
    __syncthreads();

    // ---- horizontal pass: 74 rows x 8 quad-groups = 592 items ----
    #pragma unroll
    for (int it = 0; it < 2; it++) {
        int g = tid + it * 512;
        if (g < EH * (TW / 4)) {
            const int r  = g >> 3;
            const int c0 = (g & 7) * 4;
            __half2 aX[4], aY[4];
            #pragma unroll
            for (int j = 0; j < 4; j++) {
                aX[j] = __floats2half2_rn(0.f, 0.f);
                aY[j] = aX[j];
            }

            #pragma unroll
            for (int i = 0; i < 14; i++) {
                __half2 X = sX[r][c0 + i];
                __half2 Y = __hmul2(X, X);
                #pragma unroll
                for (int j = 0; j < 4; j++) {
                    int k = i - j;
                    if (k >= 0 && k <= 10) {
                        __half2 w2 = __float2half2_rn(GW[k]);
                        aX[j] = __hfma2(X, w2, aX[j]);
                        aY[j] = __hfma2(Y, w2, aY[j]);
                    }
                }
            }
            #pragma unroll
            for (int j = 0; j < 4; j++) {
                HQrec q; q.ab = aX[j]; q.cd = aY[j];
                hQ[r][c0 + j] = q;      // one STS.64
            }
        }
    }
    __syncthreads();

    // ---- vertical pass + SSIM: thread -> (x, 4 adjacent y) ----
    const int x  = tid & 31;
    const int y0 = (tid >> 5) * 4;     // 0..60

    __half2 vX[4], vY[4];
    #pragma unroll
    for (int j = 0; j < 4; j++) {
        vX[j] = __floats2half2_rn(0.f, 0.f);
        vY[j] = vX[j];
    }

    #pragma unroll
    for (int i = 0; i < 14; i++) {
        HQrec q = hQ[y0 + i][x];       // one LDS.64 per tap
        #pragma unroll
        for (int j = 0; j < 4; j++) {
            int k = i - j;
            if (k >= 0 && k <= 10) {
                __half2 w2 = __float2half2_rn(GW[k]);
                vX[j] = __hfma2(q.ab, w2, vX[j]);
                vY[j] = __hfma2(q.cd, w2, vY[j]);
            }
        }
    }

    float lsum = 0.f;
    const float C1 = 1e-4f;
    const float C2 = 9e-4f;
    #pragma unroll
    for (int j = 0; j < 4; j++) {
        float A  = __low2float(vX[j]);
        float B  = __high2float(vX[j]);
        float Cv = __low2float(vY[j]);
        float Dv = __high2float(vY[j]);
        float A2 = A * A;
        float B2 = B * B;
        float t2m12 = (A2 - B2) * 0.5f;
        float msum  = (A2 + B2) * 0.5f;
        float t2s12 = (Cv - Dv) * 0.5f - t2m12;
        float ssum  = (Cv + Dv) * 0.5f - msum;
        float num = (t2m12 + C1) * (t2s12 + C2);
        float den = (msum + C1) * (ssum + C2) + 1e-8f;
        lsum += __fdividef(num, den);
    }

    // ---- block reduce, unique partial slot ----
    #pragma unroll
    for (int o = 16; o; o >>= 1)
        lsum += __shfl_xor_sync(0xffffffffu, lsum, o);
    if ((tid & 31) == 0) red[tid >> 5] = lsum;
    __syncthreads();

    if (tid == 0) {
        float s = 0.f;
        #pragma unroll
        for (int w = 0; w < 16; w++) s += red[w];
        int bid = (blockIdx.z * GY + blockIdx.y) * GX + blockIdx.x;
        g_part[bid] = s;
        __threadfence();
        unsigned int prev = atomicAdd(&g_count, 1u);
        *lastflag = (prev == NBLK - 1) ? 1 : 0;
    }
    __syncthreads();

    // ---- last block: final reduction over all partials ----
    if (*lastflag) {
        __threadfence();
        const float4* p4 = (const float4*)g_part;
        float s = 0.f;
        #pragma unroll
        for (int it = 0; it < 6; it++) {
            float4 v = p4[tid + it * 512];
            s += (v.x + v.y) + (v.z + v.w);
        }
        #pragma unroll
        for (int o = 16; o; o >>= 1)
            s += __shfl_xor_sync(0xffffffffu, s, o);
        if ((tid & 31) == 0) red[tid >> 5] = s;
        __syncthreads();
        if (tid == 0) {
            float t = 0.f;
            #pragma unroll
            for (int w = 0; w < 16; w++) t += red[w];
            out[0] = (float)(1.0 - (double)t * (1.0 / N_PIX));
            g_count = 0;   // self-reset for next graph replay
        }
    }
}

extern "C" void kernel_launch(void* const* d_in, const int* in_sizes, int n_in,
                              void* d_out, int out_size)
{
    const float* pred = (const float*)d_in[0];
    const float* targ = (const float*)d_in[1];

    cudaFuncSetAttribute(ssim_tile_kernel,
                         cudaFuncAttributeMaxDynamicSharedMemorySize, SMEM_TOTAL);
    dim3 grid(GX, GY, N_PLANES);   // 16 x 8 x 96
    ssim_tile_kernel<<<grid, 512, SMEM_TOTAL>>>(pred, targ, (float*)d_out);
}